// round 14
// baseline (speedup 1.0000x reference)
#include <cuda_runtime.h>
#include <cstdint>

#define LSEQ 4096
#define DIM 768
#define HID 384
#define G4 1536
#define EN_ 32768
#define PN_ 32768
#define K3 2304   // 3*768 folded-K for pair MLP
#define NTICKET 768  // 32 bm * 12 bn * 2 dir

// ---------------- scratch (device globals; no allocation allowed) ----------------
__device__ float g_xg[2][LSEQ][G4];
__device__ float g_tok[LSEQ][2 * HID];
__device__ float g_prefix[LSEQ + 1][2 * HID];
__device__ float g_csum[32][2 * HID];
__device__ float g_evemb[EN_][2 * HID];
__device__ float g_wp[DIM][K3];
__device__ float g_h1[PN_][DIM];
__device__ float g_h2[PN_][256];
__device__ unsigned long long g_hpack[2][2][HID];  // fallback path
__device__ int g_is64[3];
__device__ int g_ticket;
__device__ int g_xgflag[2][32];

// ---------------- helpers ----------------
__device__ __forceinline__ long long fetch_idx(const void* p, int which, long long i) {
    if (g_is64[which]) return ((const long long*)p)[i];
    return (long long)((const int*)p)[i];
}
__device__ __forceinline__ float sigf(float x) { return 1.f / (1.f + __expf(-x)); }
__device__ __forceinline__ float tanh_fast(float x) {
    x = fminf(15.f, fmaxf(-15.f, x));
    float e = __expf(-2.f * x);
    return (1.f - e) / (1.f + e);
}
__device__ __forceinline__ unsigned long long ldvol64(const unsigned long long* p) {
    unsigned long long v;
    asm volatile("ld.volatile.global.b64 %0, [%1];" : "=l"(v) : "l"(p));
    return v;
}
__device__ __forceinline__ void stvol64(unsigned long long* p, unsigned long long v) {
    asm volatile("st.volatile.global.b64 [%0], %1;" :: "l"(p), "l"(v));
}
__device__ __forceinline__ int ldacq(const int* p) {
    int v;
    asm volatile("ld.global.acquire.gpu.b32 %0, [%1];" : "=r"(v) : "l"(p));
    return v;
}
__device__ __forceinline__ unsigned f2tf32(float f) {
    unsigned r;
    asm("cvt.rna.tf32.f32 %0, %1;" : "=r"(r) : "f"(f));
    return r;
}
__device__ __forceinline__ unsigned smem_u32(const void* p) {
    return (unsigned)__cvta_generic_to_shared(p);
}
__device__ __forceinline__ void st_cluster_v4(unsigned laddr, int rank, float4 v) {
    unsigned r;
    asm volatile("mapa.shared::cluster.u32 %0, %1, %2;" : "=r"(r) : "r"(laddr), "r"(rank));
    asm volatile("st.shared::cluster.v4.f32 [%0], {%1,%2,%3,%4};"
                 :: "r"(r), "f"(v.x), "f"(v.y), "f"(v.z), "f"(v.w));
}
__device__ __forceinline__ void mbar_arrive_cluster(unsigned local_mbar, int rank) {
    asm volatile(
        "{\n\t"
        ".reg .b32 ra;\n\t"
        "mapa.shared::cluster.u32 ra, %0, %1;\n\t"
        "mbarrier.arrive.shared::cluster.b64 _, [ra];\n\t"
        "}"
        :: "r"(local_mbar), "r"(rank) : "memory");
}
__device__ __forceinline__ void mbar_init(unsigned mbar, unsigned cnt) {
    asm volatile("mbarrier.init.shared.b64 [%0], %1;" :: "r"(mbar), "r"(cnt) : "memory");
}
__device__ __forceinline__ void mbar_wait_parity_cluster(unsigned mbar, unsigned ph) {
    unsigned done;
    asm volatile(
        "{\n\t"
        ".reg .pred p;\n\t"
        "mbarrier.try_wait.parity.acquire.cluster.shared::cta.b64 p, [%1], %2;\n\t"
        "selp.b32 %0, 1, 0, p;\n\t"
        "}"
        : "=r"(done) : "r"(mbar), "r"(ph) : "memory");
    while (!done) {
        asm volatile(
            "{\n\t"
            ".reg .pred p;\n\t"
            "mbarrier.try_wait.parity.acquire.cluster.shared::cta.b64 p, [%1], %2, 0x989680;\n\t"
            "selp.b32 %0, 1, 0, p;\n\t"
            "}"
            : "=r"(done) : "r"(mbar), "r"(ph) : "memory");
    }
}

// ---------------- dtype detection + init ----------------
__global__ void detect_kernel(const void* lab_ev, const void* pairs, const void* labt) {
    if (threadIdx.x == 0) {
        const int* a = (const int*)lab_ev;
        int nz = 0;
        for (int i = 0; i < 64; i++) nz |= a[2 * i + 1];
        g_is64[0] = (nz == 0);
        const int* b = (const int*)pairs;
        nz = 0;
        for (int i = 0; i < 64; i++) nz |= b[2 * i + 1];
        g_is64[1] = (nz == 0);
        const int* c = (const int*)labt;
        nz = 0;
        for (int i = 0; i < 64; i++) nz |= c[2 * i + 1];
        g_is64[2] = (nz == 0);
    }
}

__global__ void init_kernel(float* out, int loss_off) {
    int i = blockIdx.x * blockDim.x + threadIdx.x;
    if (i < 2 * 2 * HID) ((unsigned long long*)g_hpack)[i] = 0ULL;
    if (i < 64) ((int*)g_xgflag)[i] = 0;
    if (i == 64) g_ticket = 0;
    if (i == 0 && loss_off) out[0] = 0.f;
}

#define TPAD 36

// ---------------- tf32x3 xgate tile (device body, shared by standalone + workers) --
__device__ void txg_tile(const float* __restrict__ A, const float* __restrict__ B,
                         float* __restrict__ C, unsigned* sh, int bm, int bn, int tid) {
    const int N = G4, K = DIM;
    unsigned* Ah = sh;
    unsigned* Al = Ah + 128 * TPAD;
    unsigned* Bh = Al + 128 * TPAD;
    unsigned* Bl = Bh + 128 * TPAD;
    int wid = tid >> 5, l = tid & 31;
    int wm = wid & 3, wn = wid >> 2;
    int gr = l >> 2, gc = l & 3;
    const float* Ab = A + (long long)bm * 128 * K;
    const float* Bb = B + (long long)bn * 128 * K;

    float acc[2][8][4];
#pragma unroll
    for (int mi = 0; mi < 2; mi++)
#pragma unroll
        for (int ni = 0; ni < 8; ni++)
#pragma unroll
            for (int c = 0; c < 4; c++) acc[mi][ni][c] = 0.f;

    int row[4], qk[4];
    float4 ra[4], rb[4];
#pragma unroll
    for (int i = 0; i < 4; i++) {
        int idx = tid + i * 256;
        row[i] = idx >> 3;
        qk[i] = idx & 7;
        ra[i] = *(const float4*)(Ab + (long long)row[i] * K + qk[i] * 4);
        rb[i] = *(const float4*)(Bb + (long long)row[i] * K + qk[i] * 4);
    }

    for (int k0 = 0; k0 < K; k0 += 32) {
#pragma unroll
        for (int i = 0; i < 4; i++) {
            int base = row[i] * TPAD + qk[i] * 4;
            float av[4] = {ra[i].x, ra[i].y, ra[i].z, ra[i].w};
            float bv[4] = {rb[i].x, rb[i].y, rb[i].z, rb[i].w};
#pragma unroll
            for (int c = 0; c < 4; c++) {
                unsigned ah = f2tf32(av[c]);
                Ah[base + c] = ah;
                Al[base + c] = f2tf32(av[c] - __uint_as_float(ah));
                unsigned bh = f2tf32(bv[c]);
                Bh[base + c] = bh;
                Bl[base + c] = f2tf32(bv[c] - __uint_as_float(bh));
            }
        }
        __syncthreads();
        if (k0 + 32 < K) {
#pragma unroll
            for (int i = 0; i < 4; i++) {
                ra[i] = *(const float4*)(Ab + (long long)row[i] * K + (k0 + 32) + qk[i] * 4);
                rb[i] = *(const float4*)(Bb + (long long)row[i] * K + (k0 + 32) + qk[i] * 4);
            }
        }
#pragma unroll
        for (int ks = 0; ks < 4; ks++) {
            unsigned ah[2][4], al[2][4];
#pragma unroll
            for (int mi = 0; mi < 2; mi++) {
                int baseA = (wm * 32 + mi * 16 + gr) * TPAD + ks * 8 + gc;
                ah[mi][0] = Ah[baseA];
                ah[mi][1] = Ah[baseA + 8 * TPAD];
                ah[mi][2] = Ah[baseA + 4];
                ah[mi][3] = Ah[baseA + 8 * TPAD + 4];
                al[mi][0] = Al[baseA];
                al[mi][1] = Al[baseA + 8 * TPAD];
                al[mi][2] = Al[baseA + 4];
                al[mi][3] = Al[baseA + 8 * TPAD + 4];
            }
#pragma unroll
            for (int ni = 0; ni < 8; ni++) {
                int baseB = (wn * 64 + ni * 8 + gr) * TPAD + ks * 8 + gc;
                unsigned bh0 = Bh[baseB];
                unsigned bh1 = Bh[baseB + 4];
                unsigned bl0 = Bl[baseB];
                unsigned bl1 = Bl[baseB + 4];
#pragma unroll
                for (int mi = 0; mi < 2; mi++) {
                    asm volatile(
                        "mma.sync.aligned.m16n8k8.row.col.f32.tf32.tf32.f32 "
                        "{%0,%1,%2,%3}, {%4,%5,%6,%7}, {%8,%9}, {%0,%1,%2,%3};\n"
                        : "+f"(acc[mi][ni][0]), "+f"(acc[mi][ni][1]),
                          "+f"(acc[mi][ni][2]), "+f"(acc[mi][ni][3])
                        : "r"(al[mi][0]), "r"(al[mi][1]), "r"(al[mi][2]), "r"(al[mi][3]),
                          "r"(bh0), "r"(bh1));
                    asm volatile(
                        "mma.sync.aligned.m16n8k8.row.col.f32.tf32.tf32.f32 "
                        "{%0,%1,%2,%3}, {%4,%5,%6,%7}, {%8,%9}, {%0,%1,%2,%3};\n"
                        : "+f"(acc[mi][ni][0]), "+f"(acc[mi][ni][1]),
                          "+f"(acc[mi][ni][2]), "+f"(acc[mi][ni][3])
                        : "r"(ah[mi][0]), "r"(ah[mi][1]), "r"(ah[mi][2]), "r"(ah[mi][3]),
                          "r"(bl0), "r"(bl1));
                    asm volatile(
                        "mma.sync.aligned.m16n8k8.row.col.f32.tf32.tf32.f32 "
                        "{%0,%1,%2,%3}, {%4,%5,%6,%7}, {%8,%9}, {%0,%1,%2,%3};\n"
                        : "+f"(acc[mi][ni][0]), "+f"(acc[mi][ni][1]),
                          "+f"(acc[mi][ni][2]), "+f"(acc[mi][ni][3])
                        : "r"(ah[mi][0]), "r"(ah[mi][1]), "r"(ah[mi][2]), "r"(ah[mi][3]),
                          "r"(bh0), "r"(bh1));
                }
            }
        }
        __syncthreads();
    }

#pragma unroll
    for (int mi = 0; mi < 2; mi++) {
#pragma unroll
        for (int ni = 0; ni < 8; ni++) {
            int rowc = bm * 128 + wm * 32 + mi * 16 + gr;
            int colc = bn * 128 + wn * 64 + ni * 8 + 2 * gc;
            float2 v0, v1;
            v0.x = acc[mi][ni][0];
            v0.y = acc[mi][ni][1];
            v1.x = acc[mi][ni][2];
            v1.y = acc[mi][ni][3];
            *(float2*)(C + (long long)rowc * N + colc) = v0;
            *(float2*)(C + (long long)(rowc + 8) * N + colc) = v1;
        }
    }
}

// standalone wrapper (fallback path)
__global__ void __launch_bounds__(256) txg_gemm(const float* __restrict__ A,
                                                const float* __restrict__ B0,
                                                const float* __restrict__ B1,
                                                float* __restrict__ C01) {
    extern __shared__ unsigned sh[];
    const float* B = blockIdx.z ? B1 : B0;
    float* C = C01 + (long long)blockIdx.z * LSEQ * G4;
    txg_tile(A, B, C, sh, blockIdx.y, blockIdx.x, threadIdx.x);
}

// ---------------- co-kernel: LSTM (clusters 0-1) + xgate workers (clusters 2-8) ----
// Grid 144 @ 120KB dynamic smem => exactly 1 CTA per SM, single wave: LSTM CTAs
// never share an SM with workers (the R13 regression mechanism).
__global__ void __launch_bounds__(256, 1) lstm_xg_kernel(const float* __restrict__ tokemb,
                                                         const float* __restrict__ w_ih_f,
                                                         const float* __restrict__ w_ih_b,
                                                         const float* __restrict__ w_hh_f,
                                                         const float* __restrict__ b_f,
                                                         const float* __restrict__ w_hh_b,
                                                         const float* __restrict__ b_b) {
    int bid = blockIdx.x;
    int tid = threadIdx.x;

    __shared__ float h_buf[2][HID];
    __shared__ float gate_sh[96];
    __shared__ __align__(16) float stage_sh[24];
    __shared__ __align__(8) unsigned long long mb[2];
    __shared__ int tk_sh;
    extern __shared__ unsigned sh[];

    if (bid >= 32) {
        // ---- worker CTA: pull xgate tiles off the ticket queue ----
        for (;;) {
            if (tid == 0) tk_sh = atomicAdd(&g_ticket, 1);
            __syncthreads();
            int tk = tk_sh;
            __syncthreads();
            if (tk >= NTICKET) break;
            int s = tk / 24, rem = tk % 24;
            int dir = rem / 12, bn = rem % 12;
            int bm = dir ? (31 - s) : s;
            const float* B = dir ? w_ih_b : w_ih_f;
            float* C = &g_xg[dir][0][0];
            txg_tile(tokemb, B, C, sh, bm, bn, tid);
            __threadfence();
            __syncthreads();
            if (tid == 0) atomicAdd(&g_xgflag[dir][bm], 1);
        }
        return;
    }

    // ---- LSTM CTA (R12 body + progressive xg flag waits) ----
    int dir = bid >> 4;
    int cid = bid & 15;
    const float* whh = dir ? w_hh_b : w_hh_f;
    const float* bb = dir ? b_b : b_f;
    int w = tid >> 5, l = tid & 31;

    float W[12][12];
#pragma unroll
    for (int i = 0; i < 12; i++) {
        int q = w * 12 + i;
        int grow = (q / 24) * HID + cid * 24 + (q % 24);
#pragma unroll
        for (int k = 0; k < 12; k++) W[i][k] = whh[(long long)grow * HID + (l + 32 * k)];
    }
    int hidx24 = cid * 24 + tid;
    float bias4[4] = {0.f, 0.f, 0.f, 0.f};
    if (tid < 24) {
#pragma unroll
        for (int g = 0; g < 4; g++) bias4[g] = bb[g * HID + hidx24];
    }
    const float* xg = &g_xg[dir][0][0];

    unsigned mb0 = smem_u32(&mb[0]);
    unsigned mb1 = smem_u32(&mb[1]);
    if (tid == 0) {
        mbar_init(mb0, 16);
        mbar_init(mb1, 16);
    }
    for (int i = tid; i < 2 * HID; i += 256) ((float*)h_buf)[i] = 0.f;
    __syncthreads();
    asm volatile("barrier.cluster.arrive.aligned;" ::: "memory");
    asm volatile("barrier.cluster.wait.aligned;" ::: "memory");

    float cstate = 0.f;
    float xv[4] = {0.f, 0.f, 0.f, 0.f};
    if (tid < 24) {
        int trow0 = dir ? (LSEQ - 1) : 0;
        int blk0 = trow0 >> 7;
        while (ldacq(&g_xgflag[dir][blk0]) < 12) {}
#pragma unroll
        for (int g = 0; g < 4; g++)
            xv[g] = __ldg(xg + (long long)trow0 * G4 + g * HID + hidx24);
    }

    for (int t = 0; t < LSEQ; t++) {
        int trow = dir ? (LSEQ - 1 - t) : t;
        float xn[4] = {0.f, 0.f, 0.f, 0.f};
        if (tid < 24 && t + 1 < LSEQ) {
            int trn = dir ? (LSEQ - 2 - t) : (t + 1);
            int blk = trn >> 7;
            while (ldacq(&g_xgflag[dir][blk]) < 12) {}
#pragma unroll
            for (int g = 0; g < 4; g++)
                xn[g] = __ldg(xg + (long long)trn * G4 + g * HID + hidx24);
        }
        int par = t & 1;
        int parn = par ^ 1;

        float hk[12];
#pragma unroll
        for (int k = 0; k < 12; k++) hk[k] = h_buf[par][l + 32 * k];
        float a[12];
#pragma unroll
        for (int i = 0; i < 12; i++) a[i] = 0.f;
#pragma unroll
        for (int k = 0; k < 12; k++) {
            float h = hk[k];
#pragma unroll
            for (int i = 0; i < 12; i++) a[i] += W[i][k] * h;
        }

        float b6[6];
        bool hi4 = (l & 16) != 0;
#pragma unroll
        for (int i = 0; i < 6; i++) {
            float x = hi4 ? a[i + 6] : a[i];
            float y = hi4 ? a[i] : a[i + 6];
            b6[i] = x + __shfl_xor_sync(0xffffffffu, y, 16);
        }
        float c3[3];
        bool hi3 = (l & 8) != 0;
#pragma unroll
        for (int i = 0; i < 3; i++) {
            float x = hi3 ? b6[i + 3] : b6[i];
            float y = hi3 ? b6[i] : b6[i + 3];
            c3[i] = x + __shfl_xor_sync(0xffffffffu, y, 8);
        }
#pragma unroll
        for (int st = 4; st > 0; st >>= 1) {
#pragma unroll
            for (int i = 0; i < 3; i++) c3[i] += __shfl_xor_sync(0xffffffffu, c3[i], st);
        }
        if ((l & 7) == 0) {
            int r = ((l >> 4) & 1) * 6 + ((l >> 3) & 1) * 3;
            gate_sh[w * 12 + r + 0] = c3[0];
            gate_sh[w * 12 + r + 1] = c3[1];
            gate_sh[w * 12 + r + 2] = c3[2];
        }
        __syncthreads();

        unsigned mbn = parn ? mb1 : mb0;
        if (tid < 24) {
            float iv = sigf(gate_sh[tid] + xv[0] + bias4[0]);
            float fv = sigf(gate_sh[24 + tid] + xv[1] + bias4[1]);
            float gv = tanh_fast(gate_sh[48 + tid] + xv[2] + bias4[2]);
            float ov = sigf(gate_sh[72 + tid] + xv[3] + bias4[3]);
            cstate = fv * cstate + iv * gv;
            float hv = ov * tanh_fast(cstate);
            g_tok[trow][dir * HID + hidx24] = hv;
            stage_sh[tid] = hv;
        }
        __syncwarp();
        if (tid < 6) {
            float4 v = *(const float4*)&stage_sh[tid * 4];
            unsigned laddr = smem_u32(&h_buf[parn][cid * 24 + tid * 4]);
#pragma unroll
            for (int p = 0; p < 16; p++) st_cluster_v4(laddr, p, v);
        }
        __syncwarp();
        if (tid == 0) {
#pragma unroll
            for (int p = 0; p < 16; p++) mbar_arrive_cluster(mbn, p);
        }

        mbar_wait_parity_cluster(mbn, (unsigned)((t >> 1) & 1));

#pragma unroll
        for (int g = 0; g < 4; g++) xv[g] = xn[g];
    }
}

// ---------------- LSTM fallback: R6 global packed exchange ----------------
__global__ void __launch_bounds__(256, 1) lstm_kernel(const float* __restrict__ w_hh_f,
                                                      const float* __restrict__ b_f,
                                                      const float* __restrict__ w_hh_b,
                                                      const float* __restrict__ b_b) {
    int dir = blockIdx.x >> 5;
    int cid = blockIdx.x & 31;
    const float* whh = dir ? w_hh_b : w_hh_f;
    const float* bb = dir ? b_b : b_f;
    int tid = threadIdx.x;
    int w = tid >> 5, l = tid & 31;

    __shared__ float h_sh[HID];
    __shared__ float gate_sh[48];

    float W[6][12];
#pragma unroll
    for (int i = 0; i < 6; i++) {
        int q = w * 6 + i;
        int grow = (q / 12) * HID + cid * 12 + (q % 12);
#pragma unroll
        for (int k = 0; k < 12; k++) W[i][k] = whh[(long long)grow * HID + (l + 32 * k)];
    }
    int q_h = w * 6 + l;
    int gx = (l < 6) ? ((q_h / 12) * HID + cid * 12 + (q_h % 12)) : 0;
    float bias_h = (l < 6) ? bb[gx] : 0.f;
    const float* xg = &g_xg[dir][0][0];

    float cstate = 0.f;
    for (int i = tid; i < HID; i += 256) h_sh[i] = 0.f;
    __syncthreads();

    int trow0 = dir ? (LSEQ - 1) : 0;
    float xval = (l < 6) ? __ldg(xg + (long long)trow0 * G4 + gx) : 0.f;

    for (int t = 0; t < LSEQ; t++) {
        int trow = dir ? (LSEQ - 1 - t) : t;
        float xnext = 0.f;
        if (l < 6 && t + 1 < LSEQ) {
            int trn = dir ? (LSEQ - 2 - t) : (t + 1);
            xnext = __ldg(xg + (long long)trn * G4 + gx);
        }

        float hk[12];
#pragma unroll
        for (int k = 0; k < 12; k++) hk[k] = h_sh[l + 32 * k];
        float a0 = 0.f, a1 = 0.f, a2 = 0.f, a3 = 0.f, a4 = 0.f, a5 = 0.f;
#pragma unroll
        for (int k = 0; k < 12; k++) {
            float h = hk[k];
            a0 += W[0][k] * h;
            a1 += W[1][k] * h;
            a2 += W[2][k] * h;
            a3 += W[3][k] * h;
            a4 += W[4][k] * h;
            a5 += W[5][k] * h;
        }
#pragma unroll
        for (int st = 16; st > 0; st >>= 1) {
            a0 += __shfl_xor_sync(0xffffffffu, a0, st);
            a1 += __shfl_xor_sync(0xffffffffu, a1, st);
            a2 += __shfl_xor_sync(0xffffffffu, a2, st);
            a3 += __shfl_xor_sync(0xffffffffu, a3, st);
            a4 += __shfl_xor_sync(0xffffffffu, a4, st);
            a5 += __shfl_xor_sync(0xffffffffu, a5, st);
        }
        if (l < 6) {
            float my = (l == 0) ? a0 : (l == 1) ? a1 : (l == 2) ? a2
                      : (l == 3) ? a3 : (l == 4) ? a4 : a5;
            gate_sh[q_h] = my + xval + bias_h;
        }
        __syncthreads();

        int par = t & 1;
        unsigned tag = (unsigned)(t + 1);
        if (tid < 12) {
            float iv = sigf(gate_sh[tid]);
            float fv = sigf(gate_sh[12 + tid]);
            float gv = tanh_fast(gate_sh[24 + tid]);
            float ov = sigf(gate_sh[36 + tid]);
            cstate = fv * cstate + iv * gv;
            float hv = ov * tanh_fast(cstate);
            int hidx = cid * 12 + tid;
            unsigned long long pk = ((unsigned long long)tag << 32) |
                                    (unsigned)__float_as_int(hv);
            stvol64(&g_hpack[dir][par][hidx], pk);
            g_tok[trow][dir * HID + hidx] = hv;
        }

        const unsigned long long* hp = &g_hpack[dir][par][0];
        unsigned long long v1 = ldvol64(hp + tid);
        unsigned long long v2 = 0ULL;
        if (tid < 128) v2 = ldvol64(hp + tid + 256);
        while ((unsigned)(v1 >> 32) != tag) v1 = ldvol64(hp + tid);
        h_sh[tid] = __int_as_float((int)(unsigned)v1);
        if (tid < 128) {
            while ((unsigned)(v2 >> 32) != tag) v2 = ldvol64(hp + tid + 256);
            h_sh[tid + 256] = __int_as_float((int)(unsigned)v2);
        }
        __syncthreads();

        xval = xnext;
    }
}

// ---------------- tf32 tensor-core GEMM (known-good layout) ----------------
__global__ void __launch_bounds__(256) tgemm_nt(const float* __restrict__ A,
                                                const float* __restrict__ B,
                                                float* __restrict__ C,
                                                int M, int N, int K,
                                                const float* __restrict__ bias, int relu) {
    __shared__ unsigned As[128 * TPAD];
    __shared__ unsigned Bs[128 * TPAD];
    int bm = blockIdx.y, bn = blockIdx.x;
    int tid = threadIdx.x;
    int wid = tid >> 5, l = tid & 31;
    int wm = wid & 3, wn = wid >> 2;
    int gr = l >> 2, gc = l & 3;
    const float* Ab = A + (long long)bm * 128 * K;
    const float* Bb = B + (long long)bn * 128 * K;

    float acc[2][8][4];
#pragma unroll
    for (int mi = 0; mi < 2; mi++)
#pragma unroll
        for (int ni = 0; ni < 8; ni++)
#pragma unroll
            for (int c = 0; c < 4; c++) acc[mi][ni][c] = 0.f;

    int row[4], qk[4];
    float4 ra[4], rb[4];
#pragma unroll
    for (int i = 0; i < 4; i++) {
        int idx = tid + i * 256;
        row[i] = idx >> 3;
        qk[i] = idx & 7;
        ra[i] = *(const float4*)(Ab + (long long)row[i] * K + qk[i] * 4);
        rb[i] = *(const float4*)(Bb + (long long)row[i] * K + qk[i] * 4);
    }

    for (int k0 = 0; k0 < K; k0 += 32) {
#pragma unroll
        for (int i = 0; i < 4; i++) {
            int base = row[i] * TPAD + qk[i] * 4;
            As[base + 0] = f2tf32(ra[i].x);
            As[base + 1] = f2tf32(ra[i].y);
            As[base + 2] = f2tf32(ra[i].z);
            As[base + 3] = f2tf32(ra[i].w);
            Bs[base + 0] = f2tf32(rb[i].x);
            Bs[base + 1] = f2tf32(rb[i].y);
            Bs[base + 2] = f2tf32(rb[i].z);
            Bs[base + 3] = f2tf32(rb[i].w);
        }
        __syncthreads();
        if (k0 + 32 < K) {
#pragma unroll
            for (int i = 0; i < 4; i++) {
                ra[i] = *(const float4*)(Ab + (long long)row[i] * K + (k0 + 32) + qk[i] * 4);
                rb[i] = *(const float4*)(Bb + (long long)row[i] * K + (k0 + 32) + qk[i] * 4);
            }
        }
#pragma unroll
        for (int ks = 0; ks < 4; ks++) {
            unsigned a[2][4];
#pragma unroll
            for (int mi = 0; mi < 2; mi++) {
                int baseA = (wm * 32 + mi * 16 + gr) * TPAD + ks * 8 + gc;
                a[mi][0] = As[baseA];
                a[mi][1] = As[baseA + 8 * TPAD];
                a[mi][2] = As[baseA + 4];
                a[mi][3] = As[baseA + 8 * TPAD + 4];
            }
#pragma unroll
            for (int ni = 0; ni < 8; ni++) {
                int baseB = (wn * 64 + ni * 8 + gr) * TPAD + ks * 8 + gc;
                unsigned b0 = Bs[baseB];
                unsigned b1 = Bs[baseB + 4];
#pragma unroll
                for (int mi = 0; mi < 2; mi++) {
                    asm volatile(
                        "mma.sync.aligned.m16n8k8.row.col.f32.tf32.tf32.f32 "
                        "{%0,%1,%2,%3}, {%4,%5,%6,%7}, {%8,%9}, {%0,%1,%2,%3};\n"
                        : "+f"(acc[mi][ni][0]), "+f"(acc[mi][ni][1]),
                          "+f"(acc[mi][ni][2]), "+f"(acc[mi][ni][3])
                        : "r"(a[mi][0]), "r"(a[mi][1]), "r"(a[mi][2]), "r"(a[mi][3]),
                          "r"(b0), "r"(b1));
                }
            }
        }
        __syncthreads();
    }

#pragma unroll
    for (int mi = 0; mi < 2; mi++) {
#pragma unroll
        for (int ni = 0; ni < 8; ni++) {
            int rowc = bm * 128 + wm * 32 + mi * 16 + gr;
            int colc = bn * 128 + wn * 64 + ni * 8 + 2 * gc;
            float b0v = bias ? bias[colc] : 0.f;
            float b1v = bias ? bias[colc + 1] : 0.f;
            float2 v0, v1;
            v0.x = acc[mi][ni][0] + b0v;
            v0.y = acc[mi][ni][1] + b1v;
            v1.x = acc[mi][ni][2] + b0v;
            v1.y = acc[mi][ni][3] + b1v;
            if (relu) {
                v0.x = fmaxf(v0.x, 0.f);
                v0.y = fmaxf(v0.y, 0.f);
                v1.x = fmaxf(v1.x, 0.f);
                v1.y = fmaxf(v1.y, 0.f);
            }
            *(float2*)(C + (long long)rowc * N + colc) = v0;
            *(float2*)(C + (long long)(rowc + 8) * N + colc) = v1;
        }
    }
}

// ---------------- fused feat+GEMM1 (unchanged) ----------------
__device__ __forceinline__ float4 feat_lda(const int2* pr_sh, int lrow, int k) {
    int seg = k / 768, kk = k - seg * 768;
    int2 pr = pr_sh[lrow];
    if (seg == 0) return *(const float4*)&g_evemb[pr.x][kk];
    if (seg == 1) return *(const float4*)&g_evemb[pr.y][kk];
    float4 a = *(const float4*)&g_evemb[pr.x][kk];
    float4 b = *(const float4*)&g_evemb[pr.y][kk];
    return make_float4(a.x * b.x, a.y * b.y, a.z * b.z, a.w * b.w);
}

__global__ void __launch_bounds__(256) tgemm_feat(const void* __restrict__ pairs,
                                                  float* __restrict__ C,
                                                  const float* __restrict__ bias) {
    const int N = DIM, K = K3;
    __shared__ unsigned As[128 * TPAD];
    __shared__ unsigned Bs[128 * TPAD];
    __shared__ int2 pr_sh[128];
    int bm = blockIdx.y, bn = blockIdx.x;
    int tid = threadIdx.x;
    int wid = tid >> 5, l = tid & 31;
    int wm = wid & 3, wn = wid >> 2;
    int gr = l >> 2, gc = l & 3;
    const float* Bb = &g_wp[bn * 128][0];

    if (tid < 128) {
        long long p = (long long)bm * 128 + tid;
        pr_sh[tid] = make_int2((int)fetch_idx(pairs, 1, 2 * p),
                               (int)fetch_idx(pairs, 1, 2 * p + 1));
    }
    __syncthreads();

    float acc[2][8][4];
#pragma unroll
    for (int mi = 0; mi < 2; mi++)
#pragma unroll
        for (int ni = 0; ni < 8; ni++)
#pragma unroll
            for (int c = 0; c < 4; c++) acc[mi][ni][c] = 0.f;

    int row[4], qk[4];
    float4 ra[4], rb[4];
#pragma unroll
    for (int i = 0; i < 4; i++) {
        int idx = tid + i * 256;
        row[i] = idx >> 3;
        qk[i] = idx & 7;
        ra[i] = feat_lda(pr_sh, row[i], qk[i] * 4);
        rb[i] = *(const float4*)(Bb + (long long)row[i] * K + qk[i] * 4);
    }

    for (int k0 = 0; k0 < K; k0 += 32) {
#pragma unroll
        for (int i = 0; i < 4; i++) {
            int base = row[i] * TPAD + qk[i] * 4;
            As[base + 0] = f2tf32(ra[i].x);
            As[base + 1] = f2tf32(ra[i].y);
            As[base + 2] = f2tf32(ra[i].z);
            As[base + 3] = f2tf32(ra[i].w);
            Bs[base + 0] = f2tf32(rb[i].x);
            Bs[base + 1] = f2tf32(rb[i].y);
            Bs[base + 2] = f2tf32(rb[i].z);
            Bs[base + 3] = f2tf32(rb[i].w);
        }
        __syncthreads();
        if (k0 + 32 < K) {
#pragma unroll
            for (int i = 0; i < 4; i++) {
                ra[i] = feat_lda(pr_sh, row[i], (k0 + 32) + qk[i] * 4);
                rb[i] = *(const float4*)(Bb + (long long)row[i] * K + (k0 + 32) + qk[i] * 4);
            }
        }
#pragma unroll
        for (int ks = 0; ks < 4; ks++) {
            unsigned a[2][4];
#pragma unroll
            for (int mi = 0; mi < 2; mi++) {
                int baseA = (wm * 32 + mi * 16 + gr) * TPAD + ks * 8 + gc;
                a[mi][0] = As[baseA];
                a[mi][1] = As[baseA + 8 * TPAD];
                a[mi][2] = As[baseA + 4];
                a[mi][3] = As[baseA + 8 * TPAD + 4];
            }
#pragma unroll
            for (int ni = 0; ni < 8; ni++) {
                int baseB = (wn * 64 + ni * 8 + gr) * TPAD + ks * 8 + gc;
                unsigned b0 = Bs[baseB];
                unsigned b1 = Bs[baseB + 4];
#pragma unroll
                for (int mi = 0; mi < 2; mi++) {
                    asm volatile(
                        "mma.sync.aligned.m16n8k8.row.col.f32.tf32.tf32.f32 "
                        "{%0,%1,%2,%3}, {%4,%5,%6,%7}, {%8,%9}, {%0,%1,%2,%3};\n"
                        : "+f"(acc[mi][ni][0]), "+f"(acc[mi][ni][1]),
                          "+f"(acc[mi][ni][2]), "+f"(acc[mi][ni][3])
                        : "r"(a[mi][0]), "r"(a[mi][1]), "r"(a[mi][2]), "r"(a[mi][3]),
                          "r"(b0), "r"(b1));
                }
            }
        }
        __syncthreads();
    }

#pragma unroll
    for (int mi = 0; mi < 2; mi++) {
#pragma unroll
        for (int ni = 0; ni < 8; ni++) {
            int rowc = bm * 128 + wm * 32 + mi * 16 + gr;
            int colc = bn * 128 + wn * 64 + ni * 8 + 2 * gc;
            float b0v = bias[colc];
            float b1v = bias[colc + 1];
            float2 v0, v1;
            v0.x = fmaxf(acc[mi][ni][0] + b0v, 0.f);
            v0.y = fmaxf(acc[mi][ni][1] + b1v, 0.f);
            v1.x = fmaxf(acc[mi][ni][2] + b0v, 0.f);
            v1.y = fmaxf(acc[mi][ni][3] + b1v, 0.f);
            *(float2*)(C + (long long)rowc * N + colc) = v0;
            *(float2*)(C + (long long)(rowc + 8) * N + colc) = v1;
        }
    }
}

// ---------------- 3-phase parallel scan over tok ----------------
__global__ void scan1_kernel() {
    int b = blockIdx.x;
    for (int d = threadIdx.x; d < 2 * HID; d += 256) {
        float s = 0.f;
        for (int r = 0; r < 128; r++) s += g_tok[b * 128 + r][d];
        g_csum[b][d] = s;
    }
}
__global__ void scan2_kernel() {
    int d = threadIdx.x;
    float run = 0.f;
    for (int b = 0; b < 32; b++) {
        float v = g_csum[b][d];
        g_csum[b][d] = run;
        run += v;
    }
}
__global__ void scan3_kernel() {
    int b = blockIdx.x;
    for (int d = threadIdx.x; d < 2 * HID; d += 256) {
        float run = g_csum[b][d];
        if (b == 0) g_prefix[0][d] = 0.f;
        for (int r = 0; r < 128; r++) {
            run += g_tok[b * 128 + r][d];
            g_prefix[b * 128 + r + 1][d] = run;
        }
    }
}

// ---------------- event embeddings ----------------
__global__ void event_kernel(const void* __restrict__ lab_ev) {
    int d = blockIdx.x * blockDim.x + threadIdx.x;
    int e = blockIdx.y;
    if (d >= 2 * HID) return;
    long long st = fetch_idx(lab_ev, 0, 2LL * e);
    long long en = fetch_idx(lab_ev, 0, 2LL * e + 1);
    g_evemb[e][d] = (g_prefix[en][d] - g_prefix[st][d]) / (float)(en - st);
}

// ---------------- fold W1 into [A|B|C] ----------------
__global__ void wprep_kernel(const float* __restrict__ w1) {
    int k = blockIdx.x * blockDim.x + threadIdx.x;
    int n = blockIdx.y;
    if (k >= K3) return;
    int seg = k / 768, kk = k - seg * 768;
    const float* r = w1 + (long long)n * 3072;
    float v;
    if (seg == 0) v = r[kk] + r[1536 + kk];
    else if (seg == 1) v = r[768 + kk] - r[1536 + kk];
    else v = r[2304 + kk];
    g_wp[n][k] = v;
}

// ---------------- scores + log-softmax + CE + loss ----------------
__global__ void scores_kernel(const float* __restrict__ w3, const float* __restrict__ b3,
                              const void* __restrict__ labt, float* __restrict__ out,
                              int loss_off) {
    __shared__ float w3s[4][256];
    __shared__ float ce_sh[8];
    int tid = threadIdx.x;
    int wp = tid >> 5, l = tid & 31;
    for (int i = tid; i < 1024; i += 256) w3s[i >> 8][i & 255] = w3[i];
    __syncthreads();

    int p = blockIdx.x * 8 + wp;
    const float* h2r = &g_h2[p][0];
    float hv[8];
#pragma unroll
    for (int k = 0; k < 8; k++) hv[k] = h2r[l + 32 * k];
    float s[4];
#pragma unroll
    for (int j = 0; j < 4; j++) {
        float t = 0.f;
#pragma unroll
        for (int k = 0; k < 8; k++) t += hv[k] * w3s[j][l + 32 * k];
        t += __shfl_xor_sync(0xffffffffu, t, 16);
        t += __shfl_xor_sync(0xffffffffu, t, 8);
        t += __shfl_xor_sync(0xffffffffu, t, 4);
        t += __shfl_xor_sync(0xffffffffu, t, 2);
        t += __shfl_xor_sync(0xffffffffu, t, 1);
        s[j] = t + b3[j];
    }
    if (l == 0) {
        float m = fmaxf(fmaxf(s[0], s[1]), fmaxf(s[2], s[3]));
        float se = expf(s[0] - m) + expf(s[1] - m) + expf(s[2] - m) + expf(s[3] - m);
        float lse = m + logf(se);
        long long y = fetch_idx(labt, 2, p);
        float sy = (y == 0) ? s[0] : (y == 1) ? s[1] : (y == 2) ? s[2] : s[3];
        float* o = out + loss_off + 4LL * p;
        o[0] = s[0]; o[1] = s[1]; o[2] = s[2]; o[3] = s[3];
        ce_sh[wp] = lse - sy;
    }
    __syncthreads();
    if (tid == 0 && loss_off) {
        float t = 0.f;
#pragma unroll
        for (int i = 0; i < 8; i++) t += ce_sh[i];
        atomicAdd(out, t);
    }
}

// ---------------- launch ----------------
extern "C" void kernel_launch(void* const* d_in, const int* in_sizes, int n_in,
                              void* d_out, int out_size) {
    const float* tokemb = (const float*)d_in[0];
    const float* w_ih_f = (const float*)d_in[1];
    const float* w_hh_f = (const float*)d_in[2];
    const float* b_f = (const float*)d_in[3];
    const float* w_ih_b = (const float*)d_in[4];
    const float* w_hh_b = (const float*)d_in[5];
    const float* b_b = (const float*)d_in[6];
    const float* w1 = (const float*)d_in[7];
    const float* b1 = (const float*)d_in[8];
    const float* w2 = (const float*)d_in[9];
    const float* b2 = (const float*)d_in[10];
    const float* w3 = (const float*)d_in[11];
    const float* b3 = (const float*)d_in[12];
    const void* lab_ev = d_in[13];
    const void* pairs = d_in[14];
    const void* labt = d_in[15];
    float* out = (float*)d_out;
    int loss_off = (out_size > 4 * PN_) ? 1 : 0;

    void *p_xg, *p_h1, *p_h2;
    cudaGetSymbolAddress(&p_xg, g_xg);
    cudaGetSymbolAddress(&p_h1, g_h1);
    cudaGetSymbolAddress(&p_h2, g_h2);

    detect_kernel<<<1, 1>>>(lab_ev, pairs, labt);
    init_kernel<<<32, 256>>>(out, loss_off);

    int smem_tile = 4 * 128 * TPAD * 4;   // 73,728 B used by worker tiles
    int smem_excl = 120 * 1024;           // request 120KB -> exactly 1 CTA/SM

    // co-kernel: LSTM clusters + xgate worker clusters, one CTA per SM
    bool cluster_ok = false;
    {
        cudaFuncSetAttribute(lstm_xg_kernel,
                             cudaFuncAttributeNonPortableClusterSizeAllowed, 1);
        cudaFuncSetAttribute(lstm_xg_kernel,
                             cudaFuncAttributeMaxDynamicSharedMemorySize, smem_excl);
        cudaLaunchConfig_t cfg = {};
        cfg.gridDim = dim3(144, 1, 1);
        cfg.blockDim = dim3(256, 1, 1);
        cfg.dynamicSmemBytes = (size_t)smem_excl;
        cudaLaunchAttribute at[1];
        at[0].id = cudaLaunchAttributeClusterDimension;
        at[0].val.clusterDim.x = 16;
        at[0].val.clusterDim.y = 1;
        at[0].val.clusterDim.z = 1;
        cfg.attrs = at;
        cfg.numAttrs = 1;
        int nclus = 0;
        cudaError_t qe = cudaOccupancyMaxActiveClusters(&nclus, lstm_xg_kernel, &cfg);
        if (qe == cudaSuccess && nclus >= 2) {
            cluster_ok = true;
            cudaLaunchKernelEx(&cfg, lstm_xg_kernel, tokemb, w_ih_f, w_ih_b,
                               w_hh_f, b_f, w_hh_b, b_b);
        } else {
            cudaGetLastError();
        }
    }
    if (!cluster_ok) {
        cudaFuncSetAttribute(txg_gemm, cudaFuncAttributeMaxDynamicSharedMemorySize,
                             smem_tile);
        txg_gemm<<<dim3(G4 / 128, LSEQ / 128, 2), 256, smem_tile>>>(tokemb, w_ih_f, w_ih_b,
                                                                    (float*)p_xg);
        lstm_kernel<<<64, 256>>>(w_hh_f, b_f, w_hh_b, b_b);
    }

    scan1_kernel<<<32, 256>>>();
    scan2_kernel<<<1, 2 * HID>>>();
    scan3_kernel<<<32, 256>>>();
    event_kernel<<<dim3(3, EN_), 256>>>(lab_ev);

    wprep_kernel<<<dim3(9, DIM), 256>>>(w1);
    tgemm_feat<<<dim3(DIM / 128, PN_ / 128), 256>>>(pairs, (float*)p_h1, b1);
    tgemm_nt<<<dim3(256 / 128, PN_ / 128), 256>>>((const float*)p_h1, w2, (float*)p_h2,
                                                  PN_, 256, DIM, b2, 1);

    scores_kernel<<<PN_ / 8, 256>>>(w3, b3, labt, out, loss_off);
}

// round 15
// speedup vs baseline: 1.2544x; 1.2544x over previous
#include <cuda_runtime.h>
#include <cstdint>

#define LSEQ 4096
#define DIM 768
#define HID 384
#define G4 1536
#define EN_ 32768
#define PN_ 32768
#define K3 2304   // 3*768 folded-K for pair MLP

// ---------------- scratch (device globals; no allocation allowed) ----------------
__device__ float g_xg[2][LSEQ][G4];
__device__ float g_tok[LSEQ][2 * HID];
__device__ float g_prefix[LSEQ + 1][2 * HID];
__device__ float g_csum[32][2 * HID];
__device__ float g_evemb[EN_][2 * HID];
__device__ float g_wp[DIM][K3];
__device__ float g_h1[PN_][DIM];
__device__ float g_h2[PN_][256];
__device__ unsigned long long g_hpack[2][2][HID];  // fallback path: (tag<<32)|f32
__device__ int g_is64[3];

// ---------------- helpers ----------------
__device__ __forceinline__ long long fetch_idx(const void* p, int which, long long i) {
    if (g_is64[which]) return ((const long long*)p)[i];
    return (long long)((const int*)p)[i];
}
__device__ __forceinline__ float sigf(float x) { return 1.f / (1.f + __expf(-x)); }
__device__ __forceinline__ float tanh_fast(float x) {
    x = fminf(15.f, fmaxf(-15.f, x));
    float e = __expf(-2.f * x);
    return (1.f - e) / (1.f + e);
}
__device__ __forceinline__ unsigned long long ldvol64(const unsigned long long* p) {
    unsigned long long v;
    asm volatile("ld.volatile.global.b64 %0, [%1];" : "=l"(v) : "l"(p));
    return v;
}
__device__ __forceinline__ void stvol64(unsigned long long* p, unsigned long long v) {
    asm volatile("st.volatile.global.b64 [%0], %1;" :: "l"(p), "l"(v));
}
__device__ __forceinline__ unsigned f2tf32(float f) {
    unsigned r;
    asm("cvt.rna.tf32.f32 %0, %1;" : "=r"(r) : "f"(f));
    return r;
}
__device__ __forceinline__ unsigned smem_u32(const void* p) {
    return (unsigned)__cvta_generic_to_shared(p);
}
__device__ __forceinline__ void st_cluster_v4(unsigned laddr, int rank, float4 v) {
    unsigned r;
    asm volatile("mapa.shared::cluster.u32 %0, %1, %2;" : "=r"(r) : "r"(laddr), "r"(rank));
    asm volatile("st.shared::cluster.v4.f32 [%0], {%1,%2,%3,%4};"
                 :: "r"(r), "f"(v.x), "f"(v.y), "f"(v.z), "f"(v.w));
}
__device__ __forceinline__ void mbar_arrive_cluster(unsigned local_mbar, int rank) {
    asm volatile(
        "{\n\t"
        ".reg .b32 ra;\n\t"
        "mapa.shared::cluster.u32 ra, %0, %1;\n\t"
        "mbarrier.arrive.shared::cluster.b64 _, [ra];\n\t"
        "}"
        :: "r"(local_mbar), "r"(rank) : "memory");
}
__device__ __forceinline__ void mbar_init(unsigned mbar, unsigned cnt) {
    asm volatile("mbarrier.init.shared.b64 [%0], %1;" :: "r"(mbar), "r"(cnt) : "memory");
}
__device__ __forceinline__ void mbar_wait_parity_cluster(unsigned mbar, unsigned ph) {
    unsigned done;
    asm volatile(
        "{\n\t"
        ".reg .pred p;\n\t"
        "mbarrier.try_wait.parity.acquire.cluster.shared::cta.b64 p, [%1], %2;\n\t"
        "selp.b32 %0, 1, 0, p;\n\t"
        "}"
        : "=r"(done) : "r"(mbar), "r"(ph) : "memory");
    while (!done) {
        asm volatile(
            "{\n\t"
            ".reg .pred p;\n\t"
            "mbarrier.try_wait.parity.acquire.cluster.shared::cta.b64 p, [%1], %2, 0x989680;\n\t"
            "selp.b32 %0, 1, 0, p;\n\t"
            "}"
            : "=r"(done) : "r"(mbar), "r"(ph) : "memory");
    }
}

// ---------------- dtype detection + init ----------------
__global__ void detect_kernel(const void* lab_ev, const void* pairs, const void* labt) {
    if (threadIdx.x == 0) {
        const int* a = (const int*)lab_ev;
        int nz = 0;
        for (int i = 0; i < 64; i++) nz |= a[2 * i + 1];
        g_is64[0] = (nz == 0);
        const int* b = (const int*)pairs;
        nz = 0;
        for (int i = 0; i < 64; i++) nz |= b[2 * i + 1];
        g_is64[1] = (nz == 0);
        const int* c = (const int*)labt;
        nz = 0;
        for (int i = 0; i < 64; i++) nz |= c[2 * i + 1];
        g_is64[2] = (nz == 0);
    }
}

__global__ void init_kernel(float* out, int loss_off) {
    int i = blockIdx.x * blockDim.x + threadIdx.x;
    if (i < 2 * 2 * HID) ((unsigned long long*)g_hpack)[i] = 0ULL;
    if (i == 0 && loss_off) out[0] = 0.f;
}

#define TPAD 36

// ---------------- tf32x3 split-precision GEMM for xgate (both dirs, z=dir) --------
__global__ void __launch_bounds__(256) txg_gemm(const float* __restrict__ A,
                                                const float* __restrict__ B0,
                                                const float* __restrict__ B1,
                                                float* __restrict__ C01) {
    const int N = G4, K = DIM;
    extern __shared__ unsigned sh[];
    unsigned* Ah = sh;
    unsigned* Al = Ah + 128 * TPAD;
    unsigned* Bh = Al + 128 * TPAD;
    unsigned* Bl = Bh + 128 * TPAD;
    const float* B = blockIdx.z ? B1 : B0;
    float* C = C01 + (long long)blockIdx.z * LSEQ * G4;
    int bm = blockIdx.y, bn = blockIdx.x;
    int tid = threadIdx.x;
    int wid = tid >> 5, l = tid & 31;
    int wm = wid & 3, wn = wid >> 2;
    int gr = l >> 2, gc = l & 3;
    const float* Ab = A + (long long)bm * 128 * K;
    const float* Bb = B + (long long)bn * 128 * K;

    float acc[2][8][4];
#pragma unroll
    for (int mi = 0; mi < 2; mi++)
#pragma unroll
        for (int ni = 0; ni < 8; ni++)
#pragma unroll
            for (int c = 0; c < 4; c++) acc[mi][ni][c] = 0.f;

    int row[4], qk[4];
    float4 ra[4], rb[4];
#pragma unroll
    for (int i = 0; i < 4; i++) {
        int idx = tid + i * 256;
        row[i] = idx >> 3;
        qk[i] = idx & 7;
        ra[i] = *(const float4*)(Ab + (long long)row[i] * K + qk[i] * 4);
        rb[i] = *(const float4*)(Bb + (long long)row[i] * K + qk[i] * 4);
    }

    for (int k0 = 0; k0 < K; k0 += 32) {
#pragma unroll
        for (int i = 0; i < 4; i++) {
            int base = row[i] * TPAD + qk[i] * 4;
            float av[4] = {ra[i].x, ra[i].y, ra[i].z, ra[i].w};
            float bv[4] = {rb[i].x, rb[i].y, rb[i].z, rb[i].w};
#pragma unroll
            for (int c = 0; c < 4; c++) {
                unsigned ah = f2tf32(av[c]);
                Ah[base + c] = ah;
                Al[base + c] = f2tf32(av[c] - __uint_as_float(ah));
                unsigned bh = f2tf32(bv[c]);
                Bh[base + c] = bh;
                Bl[base + c] = f2tf32(bv[c] - __uint_as_float(bh));
            }
        }
        __syncthreads();
        if (k0 + 32 < K) {
#pragma unroll
            for (int i = 0; i < 4; i++) {
                ra[i] = *(const float4*)(Ab + (long long)row[i] * K + (k0 + 32) + qk[i] * 4);
                rb[i] = *(const float4*)(Bb + (long long)row[i] * K + (k0 + 32) + qk[i] * 4);
            }
        }
#pragma unroll
        for (int ks = 0; ks < 4; ks++) {
            unsigned ah[2][4], al[2][4];
#pragma unroll
            for (int mi = 0; mi < 2; mi++) {
                int baseA = (wm * 32 + mi * 16 + gr) * TPAD + ks * 8 + gc;
                ah[mi][0] = Ah[baseA];
                ah[mi][1] = Ah[baseA + 8 * TPAD];
                ah[mi][2] = Ah[baseA + 4];
                ah[mi][3] = Ah[baseA + 8 * TPAD + 4];
                al[mi][0] = Al[baseA];
                al[mi][1] = Al[baseA + 8 * TPAD];
                al[mi][2] = Al[baseA + 4];
                al[mi][3] = Al[baseA + 8 * TPAD + 4];
            }
#pragma unroll
            for (int ni = 0; ni < 8; ni++) {
                int baseB = (wn * 64 + ni * 8 + gr) * TPAD + ks * 8 + gc;
                unsigned bh0 = Bh[baseB];
                unsigned bh1 = Bh[baseB + 4];
                unsigned bl0 = Bl[baseB];
                unsigned bl1 = Bl[baseB + 4];
#pragma unroll
                for (int mi = 0; mi < 2; mi++) {
                    asm volatile(
                        "mma.sync.aligned.m16n8k8.row.col.f32.tf32.tf32.f32 "
                        "{%0,%1,%2,%3}, {%4,%5,%6,%7}, {%8,%9}, {%0,%1,%2,%3};\n"
                        : "+f"(acc[mi][ni][0]), "+f"(acc[mi][ni][1]),
                          "+f"(acc[mi][ni][2]), "+f"(acc[mi][ni][3])
                        : "r"(al[mi][0]), "r"(al[mi][1]), "r"(al[mi][2]), "r"(al[mi][3]),
                          "r"(bh0), "r"(bh1));
                    asm volatile(
                        "mma.sync.aligned.m16n8k8.row.col.f32.tf32.tf32.f32 "
                        "{%0,%1,%2,%3}, {%4,%5,%6,%7}, {%8,%9}, {%0,%1,%2,%3};\n"
                        : "+f"(acc[mi][ni][0]), "+f"(acc[mi][ni][1]),
                          "+f"(acc[mi][ni][2]), "+f"(acc[mi][ni][3])
                        : "r"(ah[mi][0]), "r"(ah[mi][1]), "r"(ah[mi][2]), "r"(ah[mi][3]),
                          "r"(bl0), "r"(bl1));
                    asm volatile(
                        "mma.sync.aligned.m16n8k8.row.col.f32.tf32.tf32.f32 "
                        "{%0,%1,%2,%3}, {%4,%5,%6,%7}, {%8,%9}, {%0,%1,%2,%3};\n"
                        : "+f"(acc[mi][ni][0]), "+f"(acc[mi][ni][1]),
                          "+f"(acc[mi][ni][2]), "+f"(acc[mi][ni][3])
                        : "r"(ah[mi][0]), "r"(ah[mi][1]), "r"(ah[mi][2]), "r"(ah[mi][3]),
                          "r"(bh0), "r"(bh1));
                }
            }
        }
        __syncthreads();
    }

#pragma unroll
    for (int mi = 0; mi < 2; mi++) {
#pragma unroll
        for (int ni = 0; ni < 8; ni++) {
            int rowc = bm * 128 + wm * 32 + mi * 16 + gr;
            int colc = bn * 128 + wn * 64 + ni * 8 + 2 * gc;
            float2 v0, v1;
            v0.x = acc[mi][ni][0];
            v0.y = acc[mi][ni][1];
            v1.x = acc[mi][ni][2];
            v1.y = acc[mi][ni][3];
            *(float2*)(C + (long long)rowc * N + colc) = v0;
            *(float2*)(C + (long long)(rowc + 8) * N + colc) = v1;
        }
    }
}

// ---------------- tf32 tensor-core GEMM (known-good layout) ----------------
__global__ void __launch_bounds__(256) tgemm_nt(const float* __restrict__ A,
                                                const float* __restrict__ B,
                                                float* __restrict__ C,
                                                int M, int N, int K,
                                                const float* __restrict__ bias, int relu) {
    __shared__ unsigned As[128 * TPAD];
    __shared__ unsigned Bs[128 * TPAD];
    int bm = blockIdx.y, bn = blockIdx.x;
    int tid = threadIdx.x;
    int wid = tid >> 5, l = tid & 31;
    int wm = wid & 3, wn = wid >> 2;
    int gr = l >> 2, gc = l & 3;
    const float* Ab = A + (long long)bm * 128 * K;
    const float* Bb = B + (long long)bn * 128 * K;

    float acc[2][8][4];
#pragma unroll
    for (int mi = 0; mi < 2; mi++)
#pragma unroll
        for (int ni = 0; ni < 8; ni++)
#pragma unroll
            for (int c = 0; c < 4; c++) acc[mi][ni][c] = 0.f;

    int row[4], qk[4];
    float4 ra[4], rb[4];
#pragma unroll
    for (int i = 0; i < 4; i++) {
        int idx = tid + i * 256;
        row[i] = idx >> 3;
        qk[i] = idx & 7;
        ra[i] = *(const float4*)(Ab + (long long)row[i] * K + qk[i] * 4);
        rb[i] = *(const float4*)(Bb + (long long)row[i] * K + qk[i] * 4);
    }

    for (int k0 = 0; k0 < K; k0 += 32) {
#pragma unroll
        for (int i = 0; i < 4; i++) {
            int base = row[i] * TPAD + qk[i] * 4;
            As[base + 0] = f2tf32(ra[i].x);
            As[base + 1] = f2tf32(ra[i].y);
            As[base + 2] = f2tf32(ra[i].z);
            As[base + 3] = f2tf32(ra[i].w);
            Bs[base + 0] = f2tf32(rb[i].x);
            Bs[base + 1] = f2tf32(rb[i].y);
            Bs[base + 2] = f2tf32(rb[i].z);
            Bs[base + 3] = f2tf32(rb[i].w);
        }
        __syncthreads();
        if (k0 + 32 < K) {
#pragma unroll
            for (int i = 0; i < 4; i++) {
                ra[i] = *(const float4*)(Ab + (long long)row[i] * K + (k0 + 32) + qk[i] * 4);
                rb[i] = *(const float4*)(Bb + (long long)row[i] * K + (k0 + 32) + qk[i] * 4);
            }
        }
#pragma unroll
        for (int ks = 0; ks < 4; ks++) {
            unsigned a[2][4];
#pragma unroll
            for (int mi = 0; mi < 2; mi++) {
                int baseA = (wm * 32 + mi * 16 + gr) * TPAD + ks * 8 + gc;
                a[mi][0] = As[baseA];
                a[mi][1] = As[baseA + 8 * TPAD];
                a[mi][2] = As[baseA + 4];
                a[mi][3] = As[baseA + 8 * TPAD + 4];
            }
#pragma unroll
            for (int ni = 0; ni < 8; ni++) {
                int baseB = (wn * 64 + ni * 8 + gr) * TPAD + ks * 8 + gc;
                unsigned b0 = Bs[baseB];
                unsigned b1 = Bs[baseB + 4];
#pragma unroll
                for (int mi = 0; mi < 2; mi++) {
                    asm volatile(
                        "mma.sync.aligned.m16n8k8.row.col.f32.tf32.tf32.f32 "
                        "{%0,%1,%2,%3}, {%4,%5,%6,%7}, {%8,%9}, {%0,%1,%2,%3};\n"
                        : "+f"(acc[mi][ni][0]), "+f"(acc[mi][ni][1]),
                          "+f"(acc[mi][ni][2]), "+f"(acc[mi][ni][3])
                        : "r"(a[mi][0]), "r"(a[mi][1]), "r"(a[mi][2]), "r"(a[mi][3]),
                          "r"(b0), "r"(b1));
                }
            }
        }
        __syncthreads();
    }

#pragma unroll
    for (int mi = 0; mi < 2; mi++) {
#pragma unroll
        for (int ni = 0; ni < 8; ni++) {
            int rowc = bm * 128 + wm * 32 + mi * 16 + gr;
            int colc = bn * 128 + wn * 64 + ni * 8 + 2 * gc;
            float b0v = bias ? bias[colc] : 0.f;
            float b1v = bias ? bias[colc + 1] : 0.f;
            float2 v0, v1;
            v0.x = acc[mi][ni][0] + b0v;
            v0.y = acc[mi][ni][1] + b1v;
            v1.x = acc[mi][ni][2] + b0v;
            v1.y = acc[mi][ni][3] + b1v;
            if (relu) {
                v0.x = fmaxf(v0.x, 0.f);
                v0.y = fmaxf(v0.y, 0.f);
                v1.x = fmaxf(v1.x, 0.f);
                v1.y = fmaxf(v1.y, 0.f);
            }
            *(float2*)(C + (long long)rowc * N + colc) = v0;
            *(float2*)(C + (long long)(rowc + 8) * N + colc) = v1;
        }
    }
}

// ---------------- fused feat+GEMM1 ----------------
__device__ __forceinline__ float4 feat_lda(const int2* pr_sh, int lrow, int k) {
    int seg = k / 768, kk = k - seg * 768;
    int2 pr = pr_sh[lrow];
    if (seg == 0) return *(const float4*)&g_evemb[pr.x][kk];
    if (seg == 1) return *(const float4*)&g_evemb[pr.y][kk];
    float4 a = *(const float4*)&g_evemb[pr.x][kk];
    float4 b = *(const float4*)&g_evemb[pr.y][kk];
    return make_float4(a.x * b.x, a.y * b.y, a.z * b.z, a.w * b.w);
}

__global__ void __launch_bounds__(256) tgemm_feat(const void* __restrict__ pairs,
                                                  float* __restrict__ C,
                                                  const float* __restrict__ bias) {
    const int N = DIM, K = K3;
    __shared__ unsigned As[128 * TPAD];
    __shared__ unsigned Bs[128 * TPAD];
    __shared__ int2 pr_sh[128];
    int bm = blockIdx.y, bn = blockIdx.x;
    int tid = threadIdx.x;
    int wid = tid >> 5, l = tid & 31;
    int wm = wid & 3, wn = wid >> 2;
    int gr = l >> 2, gc = l & 3;
    const float* Bb = &g_wp[bn * 128][0];

    if (tid < 128) {
        long long p = (long long)bm * 128 + tid;
        pr_sh[tid] = make_int2((int)fetch_idx(pairs, 1, 2 * p),
                               (int)fetch_idx(pairs, 1, 2 * p + 1));
    }
    __syncthreads();

    float acc[2][8][4];
#pragma unroll
    for (int mi = 0; mi < 2; mi++)
#pragma unroll
        for (int ni = 0; ni < 8; ni++)
#pragma unroll
            for (int c = 0; c < 4; c++) acc[mi][ni][c] = 0.f;

    int row[4], qk[4];
    float4 ra[4], rb[4];
#pragma unroll
    for (int i = 0; i < 4; i++) {
        int idx = tid + i * 256;
        row[i] = idx >> 3;
        qk[i] = idx & 7;
        ra[i] = feat_lda(pr_sh, row[i], qk[i] * 4);
        rb[i] = *(const float4*)(Bb + (long long)row[i] * K + qk[i] * 4);
    }

    for (int k0 = 0; k0 < K; k0 += 32) {
#pragma unroll
        for (int i = 0; i < 4; i++) {
            int base = row[i] * TPAD + qk[i] * 4;
            As[base + 0] = f2tf32(ra[i].x);
            As[base + 1] = f2tf32(ra[i].y);
            As[base + 2] = f2tf32(ra[i].z);
            As[base + 3] = f2tf32(ra[i].w);
            Bs[base + 0] = f2tf32(rb[i].x);
            Bs[base + 1] = f2tf32(rb[i].y);
            Bs[base + 2] = f2tf32(rb[i].z);
            Bs[base + 3] = f2tf32(rb[i].w);
        }
        __syncthreads();
        if (k0 + 32 < K) {
#pragma unroll
            for (int i = 0; i < 4; i++) {
                ra[i] = feat_lda(pr_sh, row[i], (k0 + 32) + qk[i] * 4);
                rb[i] = *(const float4*)(Bb + (long long)row[i] * K + (k0 + 32) + qk[i] * 4);
            }
        }
#pragma unroll
        for (int ks = 0; ks < 4; ks++) {
            unsigned a[2][4];
#pragma unroll
            for (int mi = 0; mi < 2; mi++) {
                int baseA = (wm * 32 + mi * 16 + gr) * TPAD + ks * 8 + gc;
                a[mi][0] = As[baseA];
                a[mi][1] = As[baseA + 8 * TPAD];
                a[mi][2] = As[baseA + 4];
                a[mi][3] = As[baseA + 8 * TPAD + 4];
            }
#pragma unroll
            for (int ni = 0; ni < 8; ni++) {
                int baseB = (wn * 64 + ni * 8 + gr) * TPAD + ks * 8 + gc;
                unsigned b0 = Bs[baseB];
                unsigned b1 = Bs[baseB + 4];
#pragma unroll
                for (int mi = 0; mi < 2; mi++) {
                    asm volatile(
                        "mma.sync.aligned.m16n8k8.row.col.f32.tf32.tf32.f32 "
                        "{%0,%1,%2,%3}, {%4,%5,%6,%7}, {%8,%9}, {%0,%1,%2,%3};\n"
                        : "+f"(acc[mi][ni][0]), "+f"(acc[mi][ni][1]),
                          "+f"(acc[mi][ni][2]), "+f"(acc[mi][ni][3])
                        : "r"(a[mi][0]), "r"(a[mi][1]), "r"(a[mi][2]), "r"(a[mi][3]),
                          "r"(b0), "r"(b1));
                }
            }
        }
        __syncthreads();
    }

#pragma unroll
    for (int mi = 0; mi < 2; mi++) {
#pragma unroll
        for (int ni = 0; ni < 8; ni++) {
            int rowc = bm * 128 + wm * 32 + mi * 16 + gr;
            int colc = bn * 128 + wn * 64 + ni * 8 + 2 * gc;
            float b0v = bias[colc];
            float b1v = bias[colc + 1];
            float2 v0, v1;
            v0.x = fmaxf(acc[mi][ni][0] + b0v, 0.f);
            v0.y = fmaxf(acc[mi][ni][1] + b1v, 0.f);
            v1.x = fmaxf(acc[mi][ni][2] + b0v, 0.f);
            v1.y = fmaxf(acc[mi][ni][3] + b1v, 0.f);
            *(float2*)(C + (long long)rowc * N + colc) = v0;
            *(float2*)(C + (long long)(rowc + 8) * N + colc) = v1;
        }
    }
}

// ---------------- LSTM: cluster-16 DSMEM + mbarrier (R12 known-good) --------------
__global__ void __launch_bounds__(256, 1) lstm_cluster_kernel(const float* __restrict__ w_hh_f,
                                                              const float* __restrict__ b_f,
                                                              const float* __restrict__ w_hh_b,
                                                              const float* __restrict__ b_b) {
    int bid = blockIdx.x;
    int dir = bid >> 4;
    int cid = bid & 15;
    const float* whh = dir ? w_hh_b : w_hh_f;
    const float* bb = dir ? b_b : b_f;
    int tid = threadIdx.x;
    int w = tid >> 5, l = tid & 31;

    __shared__ float h_buf[2][HID];
    __shared__ float gate_sh[96];
    __shared__ __align__(16) float stage_sh[24];
    __shared__ __align__(8) unsigned long long mb[2];

    float W[12][12];
#pragma unroll
    for (int i = 0; i < 12; i++) {
        int q = w * 12 + i;
        int grow = (q / 24) * HID + cid * 24 + (q % 24);
#pragma unroll
        for (int k = 0; k < 12; k++) W[i][k] = whh[(long long)grow * HID + (l + 32 * k)];
    }
    int hidx24 = cid * 24 + tid;
    float bias4[4] = {0.f, 0.f, 0.f, 0.f};
    if (tid < 24) {
#pragma unroll
        for (int g = 0; g < 4; g++) bias4[g] = bb[g * HID + hidx24];
    }
    const float* xg = &g_xg[dir][0][0];

    unsigned mb0 = smem_u32(&mb[0]);
    unsigned mb1 = smem_u32(&mb[1]);
    if (tid == 0) {
        mbar_init(mb0, 16);
        mbar_init(mb1, 16);
    }
    for (int i = tid; i < 2 * HID; i += 256) ((float*)h_buf)[i] = 0.f;
    __syncthreads();
    asm volatile("barrier.cluster.arrive.aligned;" ::: "memory");
    asm volatile("barrier.cluster.wait.aligned;" ::: "memory");

    float cstate = 0.f;
    float xv[4] = {0.f, 0.f, 0.f, 0.f};
    if (tid < 24) {
        int trow0 = dir ? (LSEQ - 1) : 0;
#pragma unroll
        for (int g = 0; g < 4; g++)
            xv[g] = __ldg(xg + (long long)trow0 * G4 + g * HID + hidx24);
    }

    for (int t = 0; t < LSEQ; t++) {
        int trow = dir ? (LSEQ - 1 - t) : t;
        float xn[4] = {0.f, 0.f, 0.f, 0.f};
        if (tid < 24 && t + 1 < LSEQ) {
            int trn = dir ? (LSEQ - 2 - t) : (t + 1);
#pragma unroll
            for (int g = 0; g < 4; g++)
                xn[g] = __ldg(xg + (long long)trn * G4 + g * HID + hidx24);
        }
        int par = t & 1;
        int parn = par ^ 1;

        // matvec from parity buffer
        float hk[12];
#pragma unroll
        for (int k = 0; k < 12; k++) hk[k] = h_buf[par][l + 32 * k];
        float a[12];
#pragma unroll
        for (int i = 0; i < 12; i++) a[i] = 0.f;
#pragma unroll
        for (int k = 0; k < 12; k++) {
            float h = hk[k];
#pragma unroll
            for (int i = 0; i < 12; i++) a[i] += W[i][k] * h;
        }

        // fold reduction: 12 -> 6 (xor16) -> 3 (xor8) -> butterfly(4,2,1)
        float b6[6];
        bool hi4 = (l & 16) != 0;
#pragma unroll
        for (int i = 0; i < 6; i++) {
            float x = hi4 ? a[i + 6] : a[i];
            float y = hi4 ? a[i] : a[i + 6];
            b6[i] = x + __shfl_xor_sync(0xffffffffu, y, 16);
        }
        float c3[3];
        bool hi3 = (l & 8) != 0;
#pragma unroll
        for (int i = 0; i < 3; i++) {
            float x = hi3 ? b6[i + 3] : b6[i];
            float y = hi3 ? b6[i] : b6[i + 3];
            c3[i] = x + __shfl_xor_sync(0xffffffffu, y, 8);
        }
#pragma unroll
        for (int st = 4; st > 0; st >>= 1) {
#pragma unroll
            for (int i = 0; i < 3; i++) c3[i] += __shfl_xor_sync(0xffffffffu, c3[i], st);
        }
        if ((l & 7) == 0) {
            int r = ((l >> 4) & 1) * 6 + ((l >> 3) & 1) * 3;
            gate_sh[w * 12 + r + 0] = c3[0];
            gate_sh[w * 12 + r + 1] = c3[1];
            gate_sh[w * 12 + r + 2] = c3[2];
        }
        __syncthreads();

        unsigned mbn = parn ? mb1 : mb0;
        if (tid < 24) {
            float iv = sigf(gate_sh[tid] + xv[0] + bias4[0]);
            float fv = sigf(gate_sh[24 + tid] + xv[1] + bias4[1]);
            float gv = tanh_fast(gate_sh[48 + tid] + xv[2] + bias4[2]);
            float ov = sigf(gate_sh[72 + tid] + xv[3] + bias4[3]);
            cstate = fv * cstate + iv * gv;
            float hv = ov * tanh_fast(cstate);
            g_tok[trow][dir * HID + hidx24] = hv;
            stage_sh[tid] = hv;
        }
        __syncwarp();
        if (tid < 6) {
            float4 v = *(const float4*)&stage_sh[tid * 4];
            unsigned laddr = smem_u32(&h_buf[parn][cid * 24 + tid * 4]);
#pragma unroll
            for (int p = 0; p < 16; p++) st_cluster_v4(laddr, p, v);
        }
        __syncwarp();
        if (tid == 0) {
#pragma unroll
            for (int p = 0; p < 16; p++) mbar_arrive_cluster(mbn, p);
        }

        mbar_wait_parity_cluster(mbn, (unsigned)((t >> 1) & 1));

#pragma unroll
        for (int g = 0; g < 4; g++) xv[g] = xn[g];
    }
}

// ---------------- LSTM fallback: R6 global packed exchange (portability only) ------
__global__ void __launch_bounds__(256, 1) lstm_kernel(const float* __restrict__ w_hh_f,
                                                      const float* __restrict__ b_f,
                                                      const float* __restrict__ w_hh_b,
                                                      const float* __restrict__ b_b) {
    int dir = blockIdx.x >> 5;
    int cid = blockIdx.x & 31;
    const float* whh = dir ? w_hh_b : w_hh_f;
    const float* bb = dir ? b_b : b_f;
    int tid = threadIdx.x;
    int w = tid >> 5, l = tid & 31;

    __shared__ float h_sh[HID];
    __shared__ float gate_sh[48];

    float W[6][12];
#pragma unroll
    for (int i = 0; i < 6; i++) {
        int q = w * 6 + i;
        int grow = (q / 12) * HID + cid * 12 + (q % 12);
#pragma unroll
        for (int k = 0; k < 12; k++) W[i][k] = whh[(long long)grow * HID + (l + 32 * k)];
    }
    int q_h = w * 6 + l;
    int gx = (l < 6) ? ((q_h / 12) * HID + cid * 12 + (q_h % 12)) : 0;
    float bias_h = (l < 6) ? bb[gx] : 0.f;
    const float* xg = &g_xg[dir][0][0];

    float cstate = 0.f;
    for (int i = tid; i < HID; i += 256) h_sh[i] = 0.f;
    __syncthreads();

    int trow0 = dir ? (LSEQ - 1) : 0;
    float xval = (l < 6) ? __ldg(xg + (long long)trow0 * G4 + gx) : 0.f;

    for (int t = 0; t < LSEQ; t++) {
        int trow = dir ? (LSEQ - 1 - t) : t;
        float xnext = 0.f;
        if (l < 6 && t + 1 < LSEQ) {
            int trn = dir ? (LSEQ - 2 - t) : (t + 1);
            xnext = __ldg(xg + (long long)trn * G4 + gx);
        }

        float hk[12];
#pragma unroll
        for (int k = 0; k < 12; k++) hk[k] = h_sh[l + 32 * k];
        float a0 = 0.f, a1 = 0.f, a2 = 0.f, a3 = 0.f, a4 = 0.f, a5 = 0.f;
#pragma unroll
        for (int k = 0; k < 12; k++) {
            float h = hk[k];
            a0 += W[0][k] * h;
            a1 += W[1][k] * h;
            a2 += W[2][k] * h;
            a3 += W[3][k] * h;
            a4 += W[4][k] * h;
            a5 += W[5][k] * h;
        }
#pragma unroll
        for (int st = 16; st > 0; st >>= 1) {
            a0 += __shfl_xor_sync(0xffffffffu, a0, st);
            a1 += __shfl_xor_sync(0xffffffffu, a1, st);
            a2 += __shfl_xor_sync(0xffffffffu, a2, st);
            a3 += __shfl_xor_sync(0xffffffffu, a3, st);
            a4 += __shfl_xor_sync(0xffffffffu, a4, st);
            a5 += __shfl_xor_sync(0xffffffffu, a5, st);
        }
        if (l < 6) {
            float my = (l == 0) ? a0 : (l == 1) ? a1 : (l == 2) ? a2
                      : (l == 3) ? a3 : (l == 4) ? a4 : a5;
            gate_sh[q_h] = my + xval + bias_h;
        }
        __syncthreads();

        int par = t & 1;
        unsigned tag = (unsigned)(t + 1);
        if (tid < 12) {
            float iv = sigf(gate_sh[tid]);
            float fv = sigf(gate_sh[12 + tid]);
            float gv = tanh_fast(gate_sh[24 + tid]);
            float ov = sigf(gate_sh[36 + tid]);
            cstate = fv * cstate + iv * gv;
            float hv = ov * tanh_fast(cstate);
            int hidx = cid * 12 + tid;
            unsigned long long pk = ((unsigned long long)tag << 32) |
                                    (unsigned)__float_as_int(hv);
            stvol64(&g_hpack[dir][par][hidx], pk);
            g_tok[trow][dir * HID + hidx] = hv;
        }

        const unsigned long long* hp = &g_hpack[dir][par][0];
        unsigned long long v1 = ldvol64(hp + tid);
        unsigned long long v2 = 0ULL;
        if (tid < 128) v2 = ldvol64(hp + tid + 256);
        while ((unsigned)(v1 >> 32) != tag) v1 = ldvol64(hp + tid);
        h_sh[tid] = __int_as_float((int)(unsigned)v1);
        if (tid < 128) {
            while ((unsigned)(v2 >> 32) != tag) v2 = ldvol64(hp + tid + 256);
            h_sh[tid + 256] = __int_as_float((int)(unsigned)v2);
        }
        __syncthreads();

        xval = xnext;
    }
}

// ---------------- 3-phase parallel scan over tok ----------------
__global__ void scan1_kernel() {
    int b = blockIdx.x;
    for (int d = threadIdx.x; d < 2 * HID; d += 256) {
        float s = 0.f;
        for (int r = 0; r < 128; r++) s += g_tok[b * 128 + r][d];
        g_csum[b][d] = s;
    }
}
__global__ void scan2_kernel() {
    int d = threadIdx.x;
    float run = 0.f;
    for (int b = 0; b < 32; b++) {
        float v = g_csum[b][d];
        g_csum[b][d] = run;
        run += v;
    }
}
__global__ void scan3_kernel() {
    int b = blockIdx.x;
    for (int d = threadIdx.x; d < 2 * HID; d += 256) {
        float run = g_csum[b][d];
        if (b == 0) g_prefix[0][d] = 0.f;
        for (int r = 0; r < 128; r++) {
            run += g_tok[b * 128 + r][d];
            g_prefix[b * 128 + r + 1][d] = run;
        }
    }
}

// ---------------- event embeddings (float4 vectorized) ----------------
__global__ void event_kernel(const void* __restrict__ lab_ev) {
    int d4 = threadIdx.x;       // 0..191 -> 4 floats each
    int e = blockIdx.y;
    if (d4 >= 192) return;
    long long st = fetch_idx(lab_ev, 0, 2LL * e);
    long long en = fetch_idx(lab_ev, 0, 2LL * e + 1);
    float inv = 1.f / (float)(en - st);
    float4 a = *(const float4*)&g_prefix[en][4 * d4];
    float4 b = *(const float4*)&g_prefix[st][4 * d4];
    float4 v;
    v.x = (a.x - b.x) * inv;
    v.y = (a.y - b.y) * inv;
    v.z = (a.z - b.z) * inv;
    v.w = (a.w - b.w) * inv;
    *(float4*)&g_evemb[e][4 * d4] = v;
}

// ---------------- fold W1 into [A|B|C] ----------------
__global__ void wprep_kernel(const float* __restrict__ w1) {
    int k = blockIdx.x * blockDim.x + threadIdx.x;
    int n = blockIdx.y;
    if (k >= K3) return;
    int seg = k / 768, kk = k - seg * 768;
    const float* r = w1 + (long long)n * 3072;
    float v;
    if (seg == 0) v = r[kk] + r[1536 + kk];
    else if (seg == 1) v = r[768 + kk] - r[1536 + kk];
    else v = r[2304 + kk];
    g_wp[n][k] = v;
}

// ---------------- scores + log-softmax + CE + loss ----------------
__global__ void scores_kernel(const float* __restrict__ w3, const float* __restrict__ b3,
                              const void* __restrict__ labt, float* __restrict__ out,
                              int loss_off) {
    __shared__ float w3s[4][256];
    __shared__ float ce_sh[8];
    int tid = threadIdx.x;
    int wp = tid >> 5, l = tid & 31;
    for (int i = tid; i < 1024; i += 256) w3s[i >> 8][i & 255] = w3[i];
    __syncthreads();

    int p = blockIdx.x * 8 + wp;
    const float* h2r = &g_h2[p][0];
    float hv[8];
#pragma unroll
    for (int k = 0; k < 8; k++) hv[k] = h2r[l + 32 * k];
    float s[4];
#pragma unroll
    for (int j = 0; j < 4; j++) {
        float t = 0.f;
#pragma unroll
        for (int k = 0; k < 8; k++) t += hv[k] * w3s[j][l + 32 * k];
        t += __shfl_xor_sync(0xffffffffu, t, 16);
        t += __shfl_xor_sync(0xffffffffu, t, 8);
        t += __shfl_xor_sync(0xffffffffu, t, 4);
        t += __shfl_xor_sync(0xffffffffu, t, 2);
        t += __shfl_xor_sync(0xffffffffu, t, 1);
        s[j] = t + b3[j];
    }
    if (l == 0) {
        float m = fmaxf(fmaxf(s[0], s[1]), fmaxf(s[2], s[3]));
        float se = expf(s[0] - m) + expf(s[1] - m) + expf(s[2] - m) + expf(s[3] - m);
        float lse = m + logf(se);
        long long y = fetch_idx(labt, 2, p);
        float sy = (y == 0) ? s[0] : (y == 1) ? s[1] : (y == 2) ? s[2] : s[3];
        float* o = out + loss_off + 4LL * p;
        o[0] = s[0]; o[1] = s[1]; o[2] = s[2]; o[3] = s[3];
        ce_sh[wp] = lse - sy;
    }
    __syncthreads();
    if (tid == 0 && loss_off) {
        float t = 0.f;
#pragma unroll
        for (int i = 0; i < 8; i++) t += ce_sh[i];
        atomicAdd(out, t);
    }
}

// ---------------- launch ----------------
extern "C" void kernel_launch(void* const* d_in, const int* in_sizes, int n_in,
                              void* d_out, int out_size) {
    const float* tokemb = (const float*)d_in[0];
    const float* w_ih_f = (const float*)d_in[1];
    const float* w_hh_f = (const float*)d_in[2];
    const float* b_f = (const float*)d_in[3];
    const float* w_ih_b = (const float*)d_in[4];
    const float* w_hh_b = (const float*)d_in[5];
    const float* b_b = (const float*)d_in[6];
    const float* w1 = (const float*)d_in[7];
    const float* b1 = (const float*)d_in[8];
    const float* w2 = (const float*)d_in[9];
    const float* b2 = (const float*)d_in[10];
    const float* w3 = (const float*)d_in[11];
    const float* b3 = (const float*)d_in[12];
    const void* lab_ev = d_in[13];
    const void* pairs = d_in[14];
    const void* labt = d_in[15];
    float* out = (float*)d_out;
    int loss_off = (out_size > 4 * PN_) ? 1 : 0;

    void *p_xg, *p_h1, *p_h2;
    cudaGetSymbolAddress(&p_xg, g_xg);
    cudaGetSymbolAddress(&p_h1, g_h1);
    cudaGetSymbolAddress(&p_h2, g_h2);

    detect_kernel<<<1, 1>>>(lab_ev, pairs, labt);
    init_kernel<<<32, 256>>>(out, loss_off);

    // xgate GEMMs: tf32x3 split-precision tensor cores, both dirs in one launch
    {
        int smem = 4 * 128 * TPAD * 4;  // 73,728 B dynamic
        cudaFuncSetAttribute(txg_gemm, cudaFuncAttributeMaxDynamicSharedMemorySize, smem);
        txg_gemm<<<dim3(G4 / 128, LSEQ / 128, 2), 256, smem>>>(tokemb, w_ih_f, w_ih_b,
                                                               (float*)p_xg);
    }

    // recurrence: cluster-16 + mbarrier exchange if supported, else fallback
    {
        cudaFuncSetAttribute(lstm_cluster_kernel,
                             cudaFuncAttributeNonPortableClusterSizeAllowed, 1);
        cudaLaunchConfig_t cfg = {};
        cfg.gridDim = dim3(32, 1, 1);
        cfg.blockDim = dim3(256, 1, 1);
        cfg.dynamicSmemBytes = 0;
        cudaLaunchAttribute at[1];
        at[0].id = cudaLaunchAttributeClusterDimension;
        at[0].val.clusterDim.x = 16;
        at[0].val.clusterDim.y = 1;
        at[0].val.clusterDim.z = 1;
        cfg.attrs = at;
        cfg.numAttrs = 1;
        int nclus = 0;
        cudaError_t qe = cudaOccupancyMaxActiveClusters(&nclus, lstm_cluster_kernel, &cfg);
        if (qe == cudaSuccess && nclus >= 2) {
            cudaLaunchKernelEx(&cfg, lstm_cluster_kernel, w_hh_f, b_f, w_hh_b, b_b);
        } else {
            cudaGetLastError();  // clear any sticky query error
            lstm_kernel<<<64, 256>>>(w_hh_f, b_f, w_hh_b, b_b);
        }
    }

    scan1_kernel<<<32, 256>>>();
    scan2_kernel<<<1, 2 * HID>>>();
    scan3_kernel<<<32, 256>>>();
    event_kernel<<<dim3(1, EN_), 192>>>(lab_ev);

    wprep_kernel<<<dim3(9, DIM), 256>>>(w1);
    tgemm_feat<<<dim3(DIM / 128, PN_ / 128), 256>>>(pairs, (float*)p_h1, b1);
    tgemm_nt<<<dim3(256 / 128, PN_ / 128), 256>>>((const float*)p_h1, w2, (float*)p_h2,
                                                  PN_, 256, DIM, b2, 1);

    scores_kernel<<<PN_ / 8, 256>>>(w3, b3, labt, out, loss_off);
}